// round 7
// baseline (speedup 1.0000x reference)
#include <cuda_runtime.h>
#include <cuda_fp16.h>
#include <cstdint>
#include <cstddef>

// Problem constants
#define T_TOK 8192
#define DHID  1024
#define NE    8
#define TK    4

// GEMM config (fp16 single pass)
#define BM    128
#define BN    128
#define BKB   64                  // k per stage
#define NST   3
#define NK    (DHID / BKB)        // 16
#define MTILES 264
#define ROWS_CAP (MTILES * BM)    // 33792

// smem stage: A 128x64 fp16 (16KB, 128B rows, XOR swizzle) + B 64x128 fp16 (16KB, 256B rows)
#define A_OFF 0
#define B_OFF 16384
#define STAGE_BYTES 32768
#define SMEM_DYN (NST * STAGE_BYTES)   // 98304

// ---------------- scratch (device globals; no allocation) ----------------
__device__ __half g_Ah[(size_t)T_TOK * DHID];            // fp16(x)
__device__ __half g_Bh[(size_t)NE * DHID * DHID];        // fp16(W), [e][k][n]
__device__ __half g_Yh[(size_t)ROWS_CAP * DHID];         // fp16 GEMM results
__device__ float g_WgT[NE * DHID];                       // Wg transposed [e][d]
__device__ int   g_pair_tok[ROWS_CAP];
__device__ int   g_slot[T_TOK * TK];
__device__ int   g_topk_e[T_TOK * TK];
__device__ float g_topk_w[T_TOK * TK];
__device__ float g_probs[T_TOK * NE];
__device__ int   g_counts[NE];
__device__ int   g_cursor[NE];
__device__ int   g_off[NE + 1];

// ---------------- PTX helpers (sm_80-compatible) ----------------
__device__ __forceinline__ uint32_t h2_as_u32(__half2 h) {
    uint32_t u;
    *(__half2*)&u = h;
    return u;
}
__device__ __forceinline__ uint32_t smem_u32(const void* p) {
    uint32_t a;
    asm("{ .reg .u64 t; cvta.to.shared.u64 t, %1; cvt.u32.u64 %0, t; }" : "=r"(a) : "l"(p));
    return a;
}
__device__ __forceinline__ void cp16(uint32_t dst, const void* src) {
    asm volatile("cp.async.cg.shared.global [%0], [%1], 16;" :: "r"(dst), "l"(src));
}
__device__ __forceinline__ void cp16z(uint32_t dst, const void* src, int sz) {
    asm volatile("cp.async.cg.shared.global [%0], [%1], 16, %2;" :: "r"(dst), "l"(src), "r"(sz));
}
#define CP_COMMIT() asm volatile("cp.async.commit_group;" ::: "memory")
#define CP_WAIT(n)  asm volatile("cp.async.wait_group %0;" :: "n"(n) : "memory")

__device__ __forceinline__ void ldsm4(uint32_t* r, uint32_t addr) {
    asm volatile("ldmatrix.sync.aligned.m8n8.x4.shared.b16 {%0,%1,%2,%3}, [%4];"
        : "=r"(r[0]), "=r"(r[1]), "=r"(r[2]), "=r"(r[3]) : "r"(addr));
}
__device__ __forceinline__ void ldsm4t(uint32_t* r, uint32_t addr) {
    asm volatile("ldmatrix.sync.aligned.m8n8.x4.trans.shared.b16 {%0,%1,%2,%3}, [%4];"
        : "=r"(r[0]), "=r"(r[1]), "=r"(r[2]), "=r"(r[3]) : "r"(addr));
}
__device__ __forceinline__ void mma16816(float* c, const uint32_t* a, const uint32_t* b) {
    asm volatile("mma.sync.aligned.m16n8k16.row.col.f32.f16.f16.f32 "
        "{%0,%1,%2,%3}, {%4,%5,%6,%7}, {%8,%9}, {%0,%1,%2,%3};"
        : "+f"(c[0]), "+f"(c[1]), "+f"(c[2]), "+f"(c[3])
        : "r"(a[0]), "r"(a[1]), "r"(a[2]), "r"(a[3]), "r"(b[0]), "r"(b[1]));
}

// ---------------- kernel 0: counters + pad fill + WgT transpose ----------------
__global__ __launch_bounds__(256) void initfill_kernel(const float* __restrict__ Wg)
{
    int i = blockIdx.x * 256 + threadIdx.x;
    if (i < NE) { g_counts[i] = 0; g_cursor[i] = 0; }
    if (i < ROWS_CAP) g_pair_tok[i] = -1;
    if (i < NE * DHID) {
        // Wg[d][e] (i = d*8+e) -> WgT[e][d]
        g_WgT[(i & 7) * DHID + (i >> 3)] = Wg[i];
    }
}

// ---------------- kernel 1: W -> fp16 and x -> fp16 (merged) ----------------
#define NW_CHUNKS ((size_t)NE * DHID * DHID / 8)   // 1048576
#define NX_CHUNKS ((size_t)T_TOK * DHID / 8)       // 1048576
__global__ __launch_bounds__(256) void conv_kernel(
    const float* __restrict__ W, const float* __restrict__ x)
{
    size_t i = (size_t)blockIdx.x * 256 + threadIdx.x;
    const float* src;
    __half* dst;
    if (i < NW_CHUNKS) { src = W + i * 8; dst = g_Bh + i * 8; }
    else { size_t j = i - NW_CHUNKS; src = x + j * 8; dst = g_Ah + j * 8; }
    float4 a = ((const float4*)src)[0], c = ((const float4*)src)[1];
    __half2 h0 = __float22half2_rn(make_float2(a.x, a.y));
    __half2 h1 = __float22half2_rn(make_float2(a.z, a.w));
    __half2 h2 = __float22half2_rn(make_float2(c.x, c.y));
    __half2 h3 = __float22half2_rn(make_float2(c.z, c.w));
    *(uint4*)dst = make_uint4(h2_as_u32(h0), h2_as_u32(h1), h2_as_u32(h2), h2_as_u32(h3));
}

// ---------------- kernel 2: router (smem WgT, warp-per-token) ----------------
__global__ __launch_bounds__(256) void router_kernel(
    const float* __restrict__ x, const float* __restrict__ bg)
{
    __shared__ float wgs[NE * DHID];   // 32KB: wgs[e*1024 + d]
    for (int i = threadIdx.x; i < NE * DHID; i += 256)
        wgs[i] = g_WgT[i];
    __syncthreads();

    int warp = threadIdx.x >> 5, lane = threadIdx.x & 31;

    for (int tt = 0; tt < 4; tt++) {
        int t = blockIdx.x * 32 + tt * 8 + warp;
        const float* xr = x + (size_t)t * DHID;

        float xv[32];
#pragma unroll
        for (int i = 0; i < 32; i++) xv[i] = xr[lane + 32 * i];

        float acc[NE];
#pragma unroll
        for (int e = 0; e < NE; e++) acc[e] = 0.f;
#pragma unroll
        for (int e = 0; e < NE; e++) {
            const float* wr = wgs + e * DHID + lane;
#pragma unroll
            for (int i = 0; i < 32; i++)
                acc[e] = fmaf(xv[i], wr[32 * i], acc[e]);
        }
#pragma unroll
        for (int off = 16; off > 0; off >>= 1)
#pragma unroll
            for (int e = 0; e < NE; e++)
                acc[e] += __shfl_down_sync(0xffffffffu, acc[e], off);

        if (lane == 0) {
            float logit[NE], p[NE];
            float mx = -1e30f;
#pragma unroll
            for (int e = 0; e < NE; e++) {
                logit[e] = acc[e] + bg[e];
                mx = fmaxf(mx, logit[e]);
            }
            float sum = 0.f;
#pragma unroll
            for (int e = 0; e < NE; e++) { p[e] = __expf(logit[e] - mx); sum += p[e]; }
            float inv = 1.0f / sum;
#pragma unroll
            for (int e = 0; e < NE; e++) { p[e] *= inv; g_probs[t * NE + e] = p[e]; }

            bool used[NE];
#pragma unroll
            for (int e = 0; e < NE; e++) used[e] = false;
            int   idxs[TK];
            float vals[TK];
            float psel = 0.f;
#pragma unroll
            for (int k = 0; k < TK; k++) {
                int best = -1; float bv = -1.f;
#pragma unroll
                for (int e = 0; e < NE; e++)
                    if (!used[e] && p[e] > bv) { bv = p[e]; best = e; }
                used[best] = true;
                idxs[k] = best; vals[k] = bv; psel += bv;
            }
            float winv = 1.0f / (psel + 1e-6f);
#pragma unroll
            for (int k = 0; k < TK; k++) {
                g_topk_e[t * TK + k] = idxs[k];
                g_topk_w[t * TK + k] = vals[k] * winv;
                atomicAdd(&g_counts[idxs[k]], 1);
            }
        }
    }
}

// ---------------- kernel 3: deterministic probs reduce + scan + aux ----------------
__global__ __launch_bounds__(256) void finalize_kernel(float* aux_out)
{
    __shared__ float sh[256];
    int tid = threadIdx.x;
    int e = tid & 7, g = tid >> 3;
    float sum = 0.f;
    for (int t = g; t < T_TOK; t += 32) sum += g_probs[t * NE + e];
    sh[tid] = sum;
    __syncthreads();
#pragma unroll
    for (int st = 128; st >= 8; st >>= 1) {
        if (tid < st) sh[tid] += sh[tid + st];
        __syncthreads();
    }
    if (tid == 0) {
        int o = 0;
        g_off[0] = 0;
#pragma unroll
        for (int i = 0; i < NE; i++) {
            o += ((g_counts[i] + BM - 1) / BM) * BM;
            g_off[i + 1] = o;
        }
        float aux = 0.f;
#pragma unroll
        for (int i = 0; i < NE; i++) aux += (float)g_counts[i] * sh[i];
        aux *= (float)NE / ((float)T_TOK * (float)T_TOK);
        if (aux_out) *aux_out = aux;
    }
}

// ---------------- kernel 4: build pair list ----------------
__global__ void build_kernel() {
    int t = blockIdx.x * blockDim.x + threadIdx.x;
    if (t >= T_TOK) return;
#pragma unroll
    for (int k = 0; k < TK; k++) {
        int e = g_topk_e[t * TK + k];
        int pos = g_off[e] + atomicAdd(&g_cursor[e], 1);
        g_pair_tok[pos] = t;
        g_slot[t * TK + k] = pos;
    }
}

// ---------------- kernel 5: grouped fp16 mma.sync GEMM ----------------
__global__ __launch_bounds__(256, 2) void gemm_kernel()
{
    extern __shared__ char dsm[];
    const int off8 = g_off[NE];
    const int m0 = blockIdx.y * BM;
    if (m0 >= off8) return;
    const int n0 = blockIdx.x * BN;
    const int tid = threadIdx.x;
    const int lane = tid & 31, wid = tid >> 5;

    int e = 0;
#pragma unroll
    for (int i = 1; i < NE; i++) if (m0 >= g_off[i]) e = i;
    const __half* __restrict__ Be = g_Bh + (size_t)e * DHID * DHID;

    const uint32_t sb = smem_u32(dsm);

    // A loader: thread t -> row t>>1, chunks (t&1)*4..+3 (16B chunks of 128B row)
    const int arow = tid >> 1;
    const int ac0  = (tid & 1) * 4;
    const int tok = g_pair_tok[m0 + arow];
    const __half* asrc0 = g_Ah + (size_t)(tok < 0 ? 0 : tok) * DHID;
    const int asz = (tok < 0) ? 0 : 16;
    // B loader: thread t -> krow t>>2, chunks (t&3)*4..+3 (16B chunks of 256B row)
    const int brow = tid >> 2;
    const int bc0  = (tid & 3) * 4;

    auto load_stage = [&](int st, int kt) {
        uint32_t stg = sb + st * STAGE_BYTES;
        int kb = kt * BKB;
        const char* as = (const char*)(asrc0 + kb + ac0 * 8);
        uint32_t ad = stg + A_OFF + arow * 128;
        int ar7 = arow & 7;
#pragma unroll
        for (int c = 0; c < 4; c++)
            cp16z(ad + (((ac0 + c) ^ ar7) << 4), as + c * 16, asz);
        const char* bs = (const char*)(Be + (size_t)(kb + brow) * DHID + n0 + bc0 * 8);
        uint32_t bd = stg + B_OFF + brow * 256;
        int br7 = brow & 7;
#pragma unroll
        for (int c = 0; c < 4; c++)
            cp16(bd + (((bc0 + c) ^ br7) << 4), bs + c * 16);
    };

    const int wm = (wid & 1) * 64;           // warp m-offset
    const int wn = (wid >> 1) * 32;          // warp n-offset

    float acc[4][4][4];
#pragma unroll
    for (int a = 0; a < 4; a++)
#pragma unroll
        for (int b = 0; b < 4; b++)
#pragma unroll
            for (int c = 0; c < 4; c++) acc[a][b][c] = 0.f;

    load_stage(0, 0); CP_COMMIT();
    load_stage(1, 1); CP_COMMIT();

    const int l15 = lane & 15;
    const int l4  = lane >> 4;

    for (int kt = 0; kt < NK; kt++) {
        if (kt + 2 < NK) load_stage((kt + 2) % NST, kt + 2);
        CP_COMMIT();
        CP_WAIT(2);
        __syncthreads();

        uint32_t stg = sb + (kt % NST) * STAGE_BYTES;
        uint32_t aB = stg + A_OFF;
        uint32_t bB = stg + B_OFF;
#pragma unroll
        for (int kk = 0; kk < 4; kk++) {
            uint32_t a[4][4], bf[2][4];
#pragma unroll
            for (int mi = 0; mi < 4; mi++) {
                int row = wm + mi * 16 + l15;
                int c = kk * 2 + l4;
                ldsm4(a[mi], aB + row * 128 + ((c ^ (row & 7)) << 4));
            }
#pragma unroll
            for (int nh = 0; nh < 2; nh++) {
                int row = kk * 16 + l15;
                int c = (wn >> 3) + nh * 2 + l4;
                ldsm4t(bf[nh], bB + row * 256 + ((c ^ (row & 7)) << 4));
            }
#pragma unroll
            for (int mi = 0; mi < 4; mi++)
#pragma unroll
                for (int nj = 0; nj < 4; nj++)
                    mma16816(acc[mi][nj], a[mi], &bf[nj >> 1][(nj & 1) * 2]);
        }
        __syncthreads();
    }

    // epilogue: registers -> g_Yh (fp16)
#pragma unroll
    for (int mi = 0; mi < 4; mi++) {
        int r0 = m0 + wm + mi * 16 + (lane >> 2);
#pragma unroll
        for (int nj = 0; nj < 4; nj++) {
            int c0 = n0 + wn + nj * 8 + (lane & 3) * 2;
            __half2 lo = __float22half2_rn(make_float2(acc[mi][nj][0], acc[mi][nj][1]));
            __half2 hi = __float22half2_rn(make_float2(acc[mi][nj][2], acc[mi][nj][3]));
            *(__half2*)(g_Yh + (size_t)r0 * DHID + c0)       = lo;
            *(__half2*)(g_Yh + (size_t)(r0 + 8) * DHID + c0) = hi;
        }
    }
}

// ---------------- kernel 6: weighted combine (fp16 Y) ----------------
__global__ __launch_bounds__(256) void combine_kernel(
    const float* __restrict__ b, float* __restrict__ out)
{
    int idx = blockIdx.x * blockDim.x + threadIdx.x;
    int t = idx >> 8;
    int f = (idx & 255) << 2;
    float4 r = make_float4(0.f, 0.f, 0.f, 0.f);
#pragma unroll
    for (int k = 0; k < TK; k++) {
        int e   = g_topk_e[t * TK + k];
        float w = g_topk_w[t * TK + k];
        int sl  = g_slot[t * TK + k];
        uint2 yraw = *(const uint2*)(g_Yh + (size_t)sl * DHID + f);
        float2 y01 = __half22float2(*(__half2*)&yraw.x);
        float2 y23 = __half22float2(*(__half2*)&yraw.y);
        float4 bv = *(const float4*)(b + (size_t)e * DHID + f);
        r.x = fmaf(w, y01.x + bv.x, r.x);
        r.y = fmaf(w, y01.y + bv.y, r.y);
        r.z = fmaf(w, y23.x + bv.z, r.z);
        r.w = fmaf(w, y23.y + bv.w, r.w);
    }
    *(float4*)(out + (size_t)t * DHID + f) = r;
}

// ---------------- launch ----------------
extern "C" void kernel_launch(void* const* d_in, const int* in_sizes, int n_in,
                              void* d_out, int out_size)
{
    const float* x  = (const float*)d_in[0];
    const float* Wg = (const float*)d_in[1];
    const float* bg = (const float*)d_in[2];
    const float* W  = (const float*)d_in[3];
    const float* b  = (const float*)d_in[4];
    float* out = (float*)d_out;

    float* aux_out = (out_size > T_TOK * DHID) ? out + (size_t)T_TOK * DHID : nullptr;

    cudaFuncSetAttribute(gemm_kernel, cudaFuncAttributeMaxDynamicSharedMemorySize, SMEM_DYN);

    initfill_kernel<<<(ROWS_CAP + 255) / 256, 256>>>(Wg);                    // 0
    conv_kernel<<<(int)((NW_CHUNKS + NX_CHUNKS) / 256), 256>>>(W, x);        // 1
    router_kernel<<<T_TOK / 32, 256>>>(x, bg);                               // 2
    finalize_kernel<<<1, 256>>>(aux_out);                                    // 3
    build_kernel<<<(T_TOK + 255) / 256, 256>>>();                            // 4
    gemm_kernel<<<dim3(DHID / BN, MTILES), 256, SMEM_DYN>>>();               // 5  <- ncu captures this
    combine_kernel<<<(T_TOK * DHID / 4 + 255) / 256, 256>>>(b, out);         // 6
}

// round 8
// speedup vs baseline: 1.0021x; 1.0021x over previous
#include <cuda_runtime.h>
#include <cuda_fp16.h>
#include <cstdint>
#include <cstddef>

// Problem constants
#define T_TOK 8192
#define DHID  1024
#define NE    8
#define TK    4

// GEMM config (fp16 single pass)
#define BM    128
#define BN    128
#define BKB   64                  // k per stage
#define NST   3
#define NK    (DHID / BKB)        // 16
#define MTILES 264
#define ROWS_CAP (MTILES * BM)    // 33792

// smem stage: A 128x64 fp16 (16KB, 128B rows, XOR swizzle) + B 64x128 fp16 (16KB, 256B rows)
#define A_OFF 0
#define B_OFF 16384
#define STAGE_BYTES 32768
#define SMEM_DYN (NST * STAGE_BYTES)   // 98304

// ---------------- scratch (device globals; no allocation) ----------------
__device__ __half g_Ah[(size_t)T_TOK * DHID];            // fp16(x)
__device__ __half g_Bh[(size_t)NE * DHID * DHID];        // fp16(W), [e][k][n]
__device__ __half g_Yh[(size_t)ROWS_CAP * DHID];         // fp16 GEMM results
__device__ float g_WgT[NE * DHID];                       // Wg transposed [e][d]
__device__ int   g_pair_tok[ROWS_CAP];
__device__ int   g_slot[T_TOK * TK];
__device__ int   g_topk_e[T_TOK * TK];
__device__ float g_topk_w[T_TOK * TK];
__device__ float g_probs[T_TOK * NE];
__device__ int   g_counts[NE];
__device__ int   g_cursor[NE];
__device__ int   g_off[NE + 1];

// ---------------- PTX helpers (sm_80-compatible) ----------------
__device__ __forceinline__ uint32_t h2_as_u32(__half2 h) {
    uint32_t u;
    *(__half2*)&u = h;
    return u;
}
__device__ __forceinline__ uint32_t smem_u32(const void* p) {
    uint32_t a;
    asm("{ .reg .u64 t; cvta.to.shared.u64 t, %1; cvt.u32.u64 %0, t; }" : "=r"(a) : "l"(p));
    return a;
}
__device__ __forceinline__ void cp16(uint32_t dst, const void* src) {
    asm volatile("cp.async.cg.shared.global [%0], [%1], 16;" :: "r"(dst), "l"(src));
}
__device__ __forceinline__ void cp16z(uint32_t dst, const void* src, int sz) {
    asm volatile("cp.async.cg.shared.global [%0], [%1], 16, %2;" :: "r"(dst), "l"(src), "r"(sz));
}
#define CP_COMMIT() asm volatile("cp.async.commit_group;" ::: "memory")
#define CP_WAIT(n)  asm volatile("cp.async.wait_group %0;" :: "n"(n) : "memory")

__device__ __forceinline__ void ldsm4(uint32_t* r, uint32_t addr) {
    asm volatile("ldmatrix.sync.aligned.m8n8.x4.shared.b16 {%0,%1,%2,%3}, [%4];"
        : "=r"(r[0]), "=r"(r[1]), "=r"(r[2]), "=r"(r[3]) : "r"(addr));
}
__device__ __forceinline__ void ldsm4t(uint32_t* r, uint32_t addr) {
    asm volatile("ldmatrix.sync.aligned.m8n8.x4.trans.shared.b16 {%0,%1,%2,%3}, [%4];"
        : "=r"(r[0]), "=r"(r[1]), "=r"(r[2]), "=r"(r[3]) : "r"(addr));
}
__device__ __forceinline__ void mma16816(float* c, const uint32_t* a, const uint32_t* b) {
    asm volatile("mma.sync.aligned.m16n8k16.row.col.f32.f16.f16.f32 "
        "{%0,%1,%2,%3}, {%4,%5,%6,%7}, {%8,%9}, {%0,%1,%2,%3};"
        : "+f"(c[0]), "+f"(c[1]), "+f"(c[2]), "+f"(c[3])
        : "r"(a[0]), "r"(a[1]), "r"(a[2]), "r"(a[3]), "r"(b[0]), "r"(b[1]));
}

// ---------------- kernel 0: counters + pad fill + WgT transpose ----------------
__global__ __launch_bounds__(256) void initfill_kernel(const float* __restrict__ Wg)
{
    int i = blockIdx.x * 256 + threadIdx.x;
    if (i < NE) { g_counts[i] = 0; g_cursor[i] = 0; }
    if (i < ROWS_CAP) g_pair_tok[i] = -1;
    if (i < NE * DHID) {
        // Wg[d][e] (i = d*8+e) -> WgT[e][d]
        g_WgT[(i & 7) * DHID + (i >> 3)] = Wg[i];
    }
}

// ---------------- kernel 1: W -> fp16 and x -> fp16 (merged) ----------------
#define NW_CHUNKS ((size_t)NE * DHID * DHID / 8)   // 1048576
#define NX_CHUNKS ((size_t)T_TOK * DHID / 8)       // 1048576
__global__ __launch_bounds__(256) void conv_kernel(
    const float* __restrict__ W, const float* __restrict__ x)
{
    size_t i = (size_t)blockIdx.x * 256 + threadIdx.x;
    const float* src;
    __half* dst;
    if (i < NW_CHUNKS) { src = W + i * 8; dst = g_Bh + i * 8; }
    else { size_t j = i - NW_CHUNKS; src = x + j * 8; dst = g_Ah + j * 8; }
    float4 a = ((const float4*)src)[0], c = ((const float4*)src)[1];
    __half2 h0 = __float22half2_rn(make_float2(a.x, a.y));
    __half2 h1 = __float22half2_rn(make_float2(a.z, a.w));
    __half2 h2 = __float22half2_rn(make_float2(c.x, c.y));
    __half2 h3 = __float22half2_rn(make_float2(c.z, c.w));
    *(uint4*)dst = make_uint4(h2_as_u32(h0), h2_as_u32(h1), h2_as_u32(h2), h2_as_u32(h3));
}

// ---------------- kernel 2: router (smem WgT, warp-per-token) ----------------
__global__ __launch_bounds__(256) void router_kernel(
    const float* __restrict__ x, const float* __restrict__ bg)
{
    __shared__ float wgs[NE * DHID];   // 32KB: wgs[e*1024 + d]
    for (int i = threadIdx.x; i < NE * DHID; i += 256)
        wgs[i] = g_WgT[i];
    __syncthreads();

    int warp = threadIdx.x >> 5, lane = threadIdx.x & 31;

    for (int tt = 0; tt < 4; tt++) {
        int t = blockIdx.x * 32 + tt * 8 + warp;
        const float* xr = x + (size_t)t * DHID;

        float xv[32];
#pragma unroll
        for (int i = 0; i < 32; i++) xv[i] = xr[lane + 32 * i];

        float acc[NE];
#pragma unroll
        for (int e = 0; e < NE; e++) acc[e] = 0.f;
#pragma unroll
        for (int e = 0; e < NE; e++) {
            const float* wr = wgs + e * DHID + lane;
#pragma unroll
            for (int i = 0; i < 32; i++)
                acc[e] = fmaf(xv[i], wr[32 * i], acc[e]);
        }
#pragma unroll
        for (int off = 16; off > 0; off >>= 1)
#pragma unroll
            for (int e = 0; e < NE; e++)
                acc[e] += __shfl_down_sync(0xffffffffu, acc[e], off);

        if (lane == 0) {
            float logit[NE], p[NE];
            float mx = -1e30f;
#pragma unroll
            for (int e = 0; e < NE; e++) {
                logit[e] = acc[e] + bg[e];
                mx = fmaxf(mx, logit[e]);
            }
            float sum = 0.f;
#pragma unroll
            for (int e = 0; e < NE; e++) { p[e] = __expf(logit[e] - mx); sum += p[e]; }
            float inv = 1.0f / sum;
#pragma unroll
            for (int e = 0; e < NE; e++) { p[e] *= inv; g_probs[t * NE + e] = p[e]; }

            bool used[NE];
#pragma unroll
            for (int e = 0; e < NE; e++) used[e] = false;
            int   idxs[TK];
            float vals[TK];
            float psel = 0.f;
#pragma unroll
            for (int k = 0; k < TK; k++) {
                int best = -1; float bv = -1.f;
#pragma unroll
                for (int e = 0; e < NE; e++)
                    if (!used[e] && p[e] > bv) { bv = p[e]; best = e; }
                used[best] = true;
                idxs[k] = best; vals[k] = bv; psel += bv;
            }
            float winv = 1.0f / (psel + 1e-6f);
#pragma unroll
            for (int k = 0; k < TK; k++) {
                g_topk_e[t * TK + k] = idxs[k];
                g_topk_w[t * TK + k] = vals[k] * winv;
                atomicAdd(&g_counts[idxs[k]], 1);
            }
        }
    }
}

// ---------------- kernel 3: deterministic probs reduce + scan + aux ----------------
__global__ __launch_bounds__(256) void finalize_kernel(float* aux_out)
{
    __shared__ float sh[256];
    int tid = threadIdx.x;
    int e = tid & 7, g = tid >> 3;
    float sum = 0.f;
    for (int t = g; t < T_TOK; t += 32) sum += g_probs[t * NE + e];
    sh[tid] = sum;
    __syncthreads();
#pragma unroll
    for (int st = 128; st >= 8; st >>= 1) {
        if (tid < st) sh[tid] += sh[tid + st];
        __syncthreads();
    }
    if (tid == 0) {
        int o = 0;
        g_off[0] = 0;
#pragma unroll
        for (int i = 0; i < NE; i++) {
            o += ((g_counts[i] + BM - 1) / BM) * BM;
            g_off[i + 1] = o;
        }
        float aux = 0.f;
#pragma unroll
        for (int i = 0; i < NE; i++) aux += (float)g_counts[i] * sh[i];
        aux *= (float)NE / ((float)T_TOK * (float)T_TOK);
        if (aux_out) *aux_out = aux;
    }
}

// ---------------- kernel 4: build pair list ----------------
__global__ void build_kernel() {
    int t = blockIdx.x * blockDim.x + threadIdx.x;
    if (t >= T_TOK) return;
#pragma unroll
    for (int k = 0; k < TK; k++) {
        int e = g_topk_e[t * TK + k];
        int pos = g_off[e] + atomicAdd(&g_cursor[e], 1);
        g_pair_tok[pos] = t;
        g_slot[t * TK + k] = pos;
    }
}

// ---------------- kernel 5: grouped fp16 mma.sync GEMM ----------------
__global__ __launch_bounds__(256, 2) void gemm_kernel()
{
    extern __shared__ char dsm[];
    const int off8 = g_off[NE];
    const int m0 = blockIdx.y * BM;
    if (m0 >= off8) return;
    const int n0 = blockIdx.x * BN;
    const int tid = threadIdx.x;
    const int lane = tid & 31, wid = tid >> 5;

    int e = 0;
#pragma unroll
    for (int i = 1; i < NE; i++) if (m0 >= g_off[i]) e = i;
    const __half* __restrict__ Be = g_Bh + (size_t)e * DHID * DHID;

    const uint32_t sb = smem_u32(dsm);

    // A loader: thread t -> row t>>1, chunks (t&1)*4..+3 (16B chunks of 128B row)
    const int arow = tid >> 1;
    const int ac0  = (tid & 1) * 4;
    const int tok = g_pair_tok[m0 + arow];
    const __half* asrc0 = g_Ah + (size_t)(tok < 0 ? 0 : tok) * DHID;
    const int asz = (tok < 0) ? 0 : 16;
    // B loader: thread t -> krow t>>2, chunks (t&3)*4..+3 (16B chunks of 256B row)
    const int brow = tid >> 2;
    const int bc0  = (tid & 3) * 4;

    auto load_stage = [&](int st, int kt) {
        uint32_t stg = sb + st * STAGE_BYTES;
        int kb = kt * BKB;
        const char* as = (const char*)(asrc0 + kb + ac0 * 8);
        uint32_t ad = stg + A_OFF + arow * 128;
        int ar7 = arow & 7;
#pragma unroll
        for (int c = 0; c < 4; c++)
            cp16z(ad + (((ac0 + c) ^ ar7) << 4), as + c * 16, asz);
        const char* bs = (const char*)(Be + (size_t)(kb + brow) * DHID + n0 + bc0 * 8);
        uint32_t bd = stg + B_OFF + brow * 256;
        int br7 = brow & 7;
#pragma unroll
        for (int c = 0; c < 4; c++)
            cp16(bd + (((bc0 + c) ^ br7) << 4), bs + c * 16);
    };

    const int wm = (wid & 1) * 64;           // warp m-offset
    const int wn = (wid >> 1) * 32;          // warp n-offset

    float acc[4][4][4];
#pragma unroll
    for (int a = 0; a < 4; a++)
#pragma unroll
        for (int b = 0; b < 4; b++)
#pragma unroll
            for (int c = 0; c < 4; c++) acc[a][b][c] = 0.f;

    load_stage(0, 0); CP_COMMIT();
    load_stage(1, 1); CP_COMMIT();

    const int l15 = lane & 15;
    const int l4  = lane >> 4;

    for (int kt = 0; kt < NK; kt++) {
        if (kt + 2 < NK) load_stage((kt + 2) % NST, kt + 2);
        CP_COMMIT();
        CP_WAIT(2);
        __syncthreads();

        uint32_t stg = sb + (kt % NST) * STAGE_BYTES;
        uint32_t aB = stg + A_OFF;
        uint32_t bB = stg + B_OFF;
#pragma unroll
        for (int kk = 0; kk < 4; kk++) {
            uint32_t a[4][4], bf[2][4];
#pragma unroll
            for (int mi = 0; mi < 4; mi++) {
                int row = wm + mi * 16 + l15;
                int c = kk * 2 + l4;
                ldsm4(a[mi], aB + row * 128 + ((c ^ (row & 7)) << 4));
            }
#pragma unroll
            for (int nh = 0; nh < 2; nh++) {
                int row = kk * 16 + l15;
                int c = (wn >> 3) + nh * 2 + l4;
                ldsm4t(bf[nh], bB + row * 256 + ((c ^ (row & 7)) << 4));
            }
#pragma unroll
            for (int mi = 0; mi < 4; mi++)
#pragma unroll
                for (int nj = 0; nj < 4; nj++)
                    mma16816(acc[mi][nj], a[mi], &bf[nj >> 1][(nj & 1) * 2]);
        }
        __syncthreads();
    }

    // epilogue: registers -> g_Yh (fp16)
#pragma unroll
    for (int mi = 0; mi < 4; mi++) {
        int r0 = m0 + wm + mi * 16 + (lane >> 2);
#pragma unroll
        for (int nj = 0; nj < 4; nj++) {
            int c0 = n0 + wn + nj * 8 + (lane & 3) * 2;
            __half2 lo = __float22half2_rn(make_float2(acc[mi][nj][0], acc[mi][nj][1]));
            __half2 hi = __float22half2_rn(make_float2(acc[mi][nj][2], acc[mi][nj][3]));
            *(__half2*)(g_Yh + (size_t)r0 * DHID + c0)       = lo;
            *(__half2*)(g_Yh + (size_t)(r0 + 8) * DHID + c0) = hi;
        }
    }
}

// ---------------- kernel 6: weighted combine (fp16 Y) ----------------
__global__ __launch_bounds__(256) void combine_kernel(
    const float* __restrict__ b, float* __restrict__ out)
{
    int idx = blockIdx.x * blockDim.x + threadIdx.x;
    int t = idx >> 8;
    int f = (idx & 255) << 2;
    float4 r = make_float4(0.f, 0.f, 0.f, 0.f);
#pragma unroll
    for (int k = 0; k < TK; k++) {
        int e   = g_topk_e[t * TK + k];
        float w = g_topk_w[t * TK + k];
        int sl  = g_slot[t * TK + k];
        uint2 yraw = *(const uint2*)(g_Yh + (size_t)sl * DHID + f);
        float2 y01 = __half22float2(*(__half2*)&yraw.x);
        float2 y23 = __half22float2(*(__half2*)&yraw.y);
        float4 bv = *(const float4*)(b + (size_t)e * DHID + f);
        r.x = fmaf(w, y01.x + bv.x, r.x);
        r.y = fmaf(w, y01.y + bv.y, r.y);
        r.z = fmaf(w, y23.x + bv.z, r.z);
        r.w = fmaf(w, y23.y + bv.w, r.w);
    }
    *(float4*)(out + (size_t)t * DHID + f) = r;
}

// ---------------- launch ----------------
extern "C" void kernel_launch(void* const* d_in, const int* in_sizes, int n_in,
                              void* d_out, int out_size)
{
    const float* x  = (const float*)d_in[0];
    const float* Wg = (const float*)d_in[1];
    const float* bg = (const float*)d_in[2];
    const float* W  = (const float*)d_in[3];
    const float* b  = (const float*)d_in[4];
    float* out = (float*)d_out;

    float* aux_out = (out_size > T_TOK * DHID) ? out + (size_t)T_TOK * DHID : nullptr;

    cudaFuncSetAttribute(gemm_kernel, cudaFuncAttributeMaxDynamicSharedMemorySize, SMEM_DYN);

    initfill_kernel<<<(ROWS_CAP + 255) / 256, 256>>>(Wg);                    // 0
    conv_kernel<<<(int)((NW_CHUNKS + NX_CHUNKS) / 256), 256>>>(W, x);        // 1
    router_kernel<<<T_TOK / 32, 256>>>(x, bg);                               // 2
    finalize_kernel<<<1, 256>>>(aux_out);                                    // 3
    build_kernel<<<(T_TOK + 255) / 256, 256>>>();                            // 4
    gemm_kernel<<<dim3(DHID / BN, MTILES), 256, SMEM_DYN>>>();               // 5  <- ncu captures this
    combine_kernel<<<(T_TOK * DHID / 4 + 255) / 256, 256>>>(b, out);         // 6
}

// round 9
// speedup vs baseline: 1.0023x; 1.0002x over previous
#include <cuda_runtime.h>
#include <cuda_fp16.h>
#include <cstdint>
#include <cstddef>

// Problem constants
#define T_TOK 8192
#define DHID  1024
#define NE    8
#define TK    4

// GEMM config (fp16 single pass)
#define BM    128
#define BN    128
#define BKB   64                  // k per stage
#define NST   3
#define NK    (DHID / BKB)        // 16
#define MTILES 264
#define ROWS_CAP (MTILES * BM)    // 33792

// smem stage: A 128x64 fp16 (16KB, 128B rows, XOR swizzle) + B 64x128 fp16 (16KB, 256B rows)
#define A_OFF 0
#define B_OFF 16384
#define STAGE_BYTES 32768
#define SMEM_DYN (NST * STAGE_BYTES)   // 98304

// ---------------- scratch (device globals; no allocation) ----------------
__device__ __half g_Ah[(size_t)T_TOK * DHID];            // fp16(x)
__device__ __half g_Bh[(size_t)NE * DHID * DHID];        // fp16(W), [e][k][n]
__device__ __half g_Yh[(size_t)ROWS_CAP * DHID];         // fp16 GEMM results
__device__ float g_WgT[NE * DHID];                       // Wg transposed [e][d]
__device__ int   g_pair_tok[ROWS_CAP];
__device__ int   g_slot[T_TOK * TK];
__device__ int   g_topk_e[T_TOK * TK];
__device__ float g_topk_w[T_TOK * TK];
__device__ float g_probs[T_TOK * NE];
__device__ int   g_counts[NE];
__device__ int   g_cursor[NE];
__device__ int   g_off[NE + 1];

// ---------------- PTX helpers (sm_80-compatible) ----------------
__device__ __forceinline__ uint32_t h2_as_u32(__half2 h) {
    uint32_t u;
    *(__half2*)&u = h;
    return u;
}
__device__ __forceinline__ uint32_t smem_u32(const void* p) {
    uint32_t a;
    asm("{ .reg .u64 t; cvta.to.shared.u64 t, %1; cvt.u32.u64 %0, t; }" : "=r"(a) : "l"(p));
    return a;
}
__device__ __forceinline__ void cp16(uint32_t dst, const void* src) {
    asm volatile("cp.async.cg.shared.global [%0], [%1], 16;" :: "r"(dst), "l"(src));
}
__device__ __forceinline__ void cp16z(uint32_t dst, const void* src, int sz) {
    asm volatile("cp.async.cg.shared.global [%0], [%1], 16, %2;" :: "r"(dst), "l"(src), "r"(sz));
}
#define CP_COMMIT() asm volatile("cp.async.commit_group;" ::: "memory")
#define CP_WAIT(n)  asm volatile("cp.async.wait_group %0;" :: "n"(n) : "memory")

__device__ __forceinline__ void ldsm4(uint32_t* r, uint32_t addr) {
    asm volatile("ldmatrix.sync.aligned.m8n8.x4.shared.b16 {%0,%1,%2,%3}, [%4];"
        : "=r"(r[0]), "=r"(r[1]), "=r"(r[2]), "=r"(r[3]) : "r"(addr));
}
__device__ __forceinline__ void ldsm4t(uint32_t* r, uint32_t addr) {
    asm volatile("ldmatrix.sync.aligned.m8n8.x4.trans.shared.b16 {%0,%1,%2,%3}, [%4];"
        : "=r"(r[0]), "=r"(r[1]), "=r"(r[2]), "=r"(r[3]) : "r"(addr));
}
__device__ __forceinline__ void mma16816(float* c, const uint32_t* a, const uint32_t* b) {
    asm volatile("mma.sync.aligned.m16n8k16.row.col.f32.f16.f16.f32 "
        "{%0,%1,%2,%3}, {%4,%5,%6,%7}, {%8,%9}, {%0,%1,%2,%3};"
        : "+f"(c[0]), "+f"(c[1]), "+f"(c[2]), "+f"(c[3])
        : "r"(a[0]), "r"(a[1]), "r"(a[2]), "r"(a[3]), "r"(b[0]), "r"(b[1]));
}

// ---------------- kernel 0: counters + pad fill + WgT transpose ----------------
__global__ __launch_bounds__(256) void initfill_kernel(const float* __restrict__ Wg)
{
    int i = blockIdx.x * 256 + threadIdx.x;
    if (i < NE) { g_counts[i] = 0; g_cursor[i] = 0; }
    if (i < ROWS_CAP) g_pair_tok[i] = -1;
    if (i < NE * DHID) {
        // Wg[d][e] (i = d*8+e) -> WgT[e][d]
        g_WgT[(i & 7) * DHID + (i >> 3)] = Wg[i];
    }
}

// ---------------- kernel 1: W -> fp16 and x -> fp16 (merged) ----------------
#define NW_CHUNKS ((size_t)NE * DHID * DHID / 8)   // 1048576
#define NX_CHUNKS ((size_t)T_TOK * DHID / 8)       // 1048576
__global__ __launch_bounds__(256) void conv_kernel(
    const float* __restrict__ W, const float* __restrict__ x)
{
    size_t i = (size_t)blockIdx.x * 256 + threadIdx.x;
    const float* src;
    __half* dst;
    if (i < NW_CHUNKS) { src = W + i * 8; dst = g_Bh + i * 8; }
    else { size_t j = i - NW_CHUNKS; src = x + j * 8; dst = g_Ah + j * 8; }
    float4 a = ((const float4*)src)[0], c = ((const float4*)src)[1];
    __half2 h0 = __float22half2_rn(make_float2(a.x, a.y));
    __half2 h1 = __float22half2_rn(make_float2(a.z, a.w));
    __half2 h2 = __float22half2_rn(make_float2(c.x, c.y));
    __half2 h3 = __float22half2_rn(make_float2(c.z, c.w));
    *(uint4*)dst = make_uint4(h2_as_u32(h0), h2_as_u32(h1), h2_as_u32(h2), h2_as_u32(h3));
}

// ---------------- kernel 2: router (smem WgT, warp-per-token) ----------------
__global__ __launch_bounds__(256) void router_kernel(
    const float* __restrict__ x, const float* __restrict__ bg)
{
    __shared__ float wgs[NE * DHID];   // 32KB: wgs[e*1024 + d]
    for (int i = threadIdx.x; i < NE * DHID; i += 256)
        wgs[i] = g_WgT[i];
    __syncthreads();

    int warp = threadIdx.x >> 5, lane = threadIdx.x & 31;

    for (int tt = 0; tt < 4; tt++) {
        int t = blockIdx.x * 32 + tt * 8 + warp;
        const float* xr = x + (size_t)t * DHID;

        float xv[32];
#pragma unroll
        for (int i = 0; i < 32; i++) xv[i] = xr[lane + 32 * i];

        float acc[NE];
#pragma unroll
        for (int e = 0; e < NE; e++) acc[e] = 0.f;
#pragma unroll
        for (int e = 0; e < NE; e++) {
            const float* wr = wgs + e * DHID + lane;
#pragma unroll
            for (int i = 0; i < 32; i++)
                acc[e] = fmaf(xv[i], wr[32 * i], acc[e]);
        }
#pragma unroll
        for (int off = 16; off > 0; off >>= 1)
#pragma unroll
            for (int e = 0; e < NE; e++)
                acc[e] += __shfl_down_sync(0xffffffffu, acc[e], off);

        if (lane == 0) {
            float logit[NE], p[NE];
            float mx = -1e30f;
#pragma unroll
            for (int e = 0; e < NE; e++) {
                logit[e] = acc[e] + bg[e];
                mx = fmaxf(mx, logit[e]);
            }
            float sum = 0.f;
#pragma unroll
            for (int e = 0; e < NE; e++) { p[e] = __expf(logit[e] - mx); sum += p[e]; }
            float inv = 1.0f / sum;
#pragma unroll
            for (int e = 0; e < NE; e++) { p[e] *= inv; g_probs[t * NE + e] = p[e]; }

            bool used[NE];
#pragma unroll
            for (int e = 0; e < NE; e++) used[e] = false;
            int   idxs[TK];
            float vals[TK];
            float psel = 0.f;
#pragma unroll
            for (int k = 0; k < TK; k++) {
                int best = -1; float bv = -1.f;
#pragma unroll
                for (int e = 0; e < NE; e++)
                    if (!used[e] && p[e] > bv) { bv = p[e]; best = e; }
                used[best] = true;
                idxs[k] = best; vals[k] = bv; psel += bv;
            }
            float winv = 1.0f / (psel + 1e-6f);
#pragma unroll
            for (int k = 0; k < TK; k++) {
                g_topk_e[t * TK + k] = idxs[k];
                g_topk_w[t * TK + k] = vals[k] * winv;
                atomicAdd(&g_counts[idxs[k]], 1);
            }
        }
    }
}

// ---------------- kernel 3: deterministic probs reduce + scan + aux ----------------
__global__ __launch_bounds__(256) void finalize_kernel(float* aux_out)
{
    __shared__ float sh[256];
    int tid = threadIdx.x;
    int e = tid & 7, g = tid >> 3;
    float sum = 0.f;
    for (int t = g; t < T_TOK; t += 32) sum += g_probs[t * NE + e];
    sh[tid] = sum;
    __syncthreads();
#pragma unroll
    for (int st = 128; st >= 8; st >>= 1) {
        if (tid < st) sh[tid] += sh[tid + st];
        __syncthreads();
    }
    if (tid == 0) {
        int o = 0;
        g_off[0] = 0;
#pragma unroll
        for (int i = 0; i < NE; i++) {
            o += ((g_counts[i] + BM - 1) / BM) * BM;
            g_off[i + 1] = o;
        }
        float aux = 0.f;
#pragma unroll
        for (int i = 0; i < NE; i++) aux += (float)g_counts[i] * sh[i];
        aux *= (float)NE / ((float)T_TOK * (float)T_TOK);
        if (aux_out) *aux_out = aux;
    }
}

// ---------------- kernel 4: build pair list ----------------
__global__ void build_kernel() {
    int t = blockIdx.x * blockDim.x + threadIdx.x;
    if (t >= T_TOK) return;
#pragma unroll
    for (int k = 0; k < TK; k++) {
        int e = g_topk_e[t * TK + k];
        int pos = g_off[e] + atomicAdd(&g_cursor[e], 1);
        g_pair_tok[pos] = t;
        g_slot[t * TK + k] = pos;
    }
}

// ---------------- kernel 5: grouped fp16 mma.sync GEMM ----------------
__global__ __launch_bounds__(256, 2) void gemm_kernel()
{
    extern __shared__ char dsm[];
    const int off8 = g_off[NE];
    const int m0 = blockIdx.y * BM;
    if (m0 >= off8) return;
    const int n0 = blockIdx.x * BN;
    const int tid = threadIdx.x;
    const int lane = tid & 31, wid = tid >> 5;

    int e = 0;
#pragma unroll
    for (int i = 1; i < NE; i++) if (m0 >= g_off[i]) e = i;
    const __half* __restrict__ Be = g_Bh + (size_t)e * DHID * DHID;

    const uint32_t sb = smem_u32(dsm);

    // A loader: thread t -> row t>>1, chunks (t&1)*4..+3 (16B chunks of 128B row)
    const int arow = tid >> 1;
    const int ac0  = (tid & 1) * 4;
    const int tok = g_pair_tok[m0 + arow];
    const __half* asrc0 = g_Ah + (size_t)(tok < 0 ? 0 : tok) * DHID;
    const int asz = (tok < 0) ? 0 : 16;
    // B loader: thread t -> krow t>>2, chunks (t&3)*4..+3 (16B chunks of 256B row)
    const int brow = tid >> 2;
    const int bc0  = (tid & 3) * 4;

    auto load_stage = [&](int st, int kt) {
        uint32_t stg = sb + st * STAGE_BYTES;
        int kb = kt * BKB;
        const char* as = (const char*)(asrc0 + kb + ac0 * 8);
        uint32_t ad = stg + A_OFF + arow * 128;
        int ar7 = arow & 7;
#pragma unroll
        for (int c = 0; c < 4; c++)
            cp16z(ad + (((ac0 + c) ^ ar7) << 4), as + c * 16, asz);
        const char* bs = (const char*)(Be + (size_t)(kb + brow) * DHID + n0 + bc0 * 8);
        uint32_t bd = stg + B_OFF + brow * 256;
        int br7 = brow & 7;
#pragma unroll
        for (int c = 0; c < 4; c++)
            cp16(bd + (((bc0 + c) ^ br7) << 4), bs + c * 16);
    };

    const int wm = (wid & 1) * 64;           // warp m-offset
    const int wn = (wid >> 1) * 32;          // warp n-offset

    float acc[4][4][4];
#pragma unroll
    for (int a = 0; a < 4; a++)
#pragma unroll
        for (int b = 0; b < 4; b++)
#pragma unroll
            for (int c = 0; c < 4; c++) acc[a][b][c] = 0.f;

    load_stage(0, 0); CP_COMMIT();
    load_stage(1, 1); CP_COMMIT();

    const int l15 = lane & 15;
    const int l4  = lane >> 4;

    for (int kt = 0; kt < NK; kt++) {
        if (kt + 2 < NK) load_stage((kt + 2) % NST, kt + 2);
        CP_COMMIT();
        CP_WAIT(2);
        __syncthreads();

        uint32_t stg = sb + (kt % NST) * STAGE_BYTES;
        uint32_t aB = stg + A_OFF;
        uint32_t bB = stg + B_OFF;
#pragma unroll
        for (int kk = 0; kk < 4; kk++) {
            uint32_t a[4][4], bf[2][4];
#pragma unroll
            for (int mi = 0; mi < 4; mi++) {
                int row = wm + mi * 16 + l15;
                int c = kk * 2 + l4;
                ldsm4(a[mi], aB + row * 128 + ((c ^ (row & 7)) << 4));
            }
#pragma unroll
            for (int nh = 0; nh < 2; nh++) {
                int row = kk * 16 + l15;
                int c = (wn >> 3) + nh * 2 + l4;
                ldsm4t(bf[nh], bB + row * 256 + ((c ^ (row & 7)) << 4));
            }
#pragma unroll
            for (int mi = 0; mi < 4; mi++)
#pragma unroll
                for (int nj = 0; nj < 4; nj++)
                    mma16816(acc[mi][nj], a[mi], &bf[nj >> 1][(nj & 1) * 2]);
        }
        __syncthreads();
    }

    // epilogue: registers -> g_Yh (fp16)
#pragma unroll
    for (int mi = 0; mi < 4; mi++) {
        int r0 = m0 + wm + mi * 16 + (lane >> 2);
#pragma unroll
        for (int nj = 0; nj < 4; nj++) {
            int c0 = n0 + wn + nj * 8 + (lane & 3) * 2;
            __half2 lo = __float22half2_rn(make_float2(acc[mi][nj][0], acc[mi][nj][1]));
            __half2 hi = __float22half2_rn(make_float2(acc[mi][nj][2], acc[mi][nj][3]));
            *(__half2*)(g_Yh + (size_t)r0 * DHID + c0)       = lo;
            *(__half2*)(g_Yh + (size_t)(r0 + 8) * DHID + c0) = hi;
        }
    }
}

// ---------------- kernel 6: weighted combine (fp16 Y) ----------------
__global__ __launch_bounds__(256) void combine_kernel(
    const float* __restrict__ b, float* __restrict__ out)
{
    int idx = blockIdx.x * blockDim.x + threadIdx.x;
    int t = idx >> 8;
    int f = (idx & 255) << 2;
    float4 r = make_float4(0.f, 0.f, 0.f, 0.f);
#pragma unroll
    for (int k = 0; k < TK; k++) {
        int e   = g_topk_e[t * TK + k];
        float w = g_topk_w[t * TK + k];
        int sl  = g_slot[t * TK + k];
        uint2 yraw = *(const uint2*)(g_Yh + (size_t)sl * DHID + f);
        float2 y01 = __half22float2(*(__half2*)&yraw.x);
        float2 y23 = __half22float2(*(__half2*)&yraw.y);
        float4 bv = *(const float4*)(b + (size_t)e * DHID + f);
        r.x = fmaf(w, y01.x + bv.x, r.x);
        r.y = fmaf(w, y01.y + bv.y, r.y);
        r.z = fmaf(w, y23.x + bv.z, r.z);
        r.w = fmaf(w, y23.y + bv.w, r.w);
    }
    *(float4*)(out + (size_t)t * DHID + f) = r;
}

// ---------------- launch ----------------
extern "C" void kernel_launch(void* const* d_in, const int* in_sizes, int n_in,
                              void* d_out, int out_size)
{
    const float* x  = (const float*)d_in[0];
    const float* Wg = (const float*)d_in[1];
    const float* bg = (const float*)d_in[2];
    const float* W  = (const float*)d_in[3];
    const float* b  = (const float*)d_in[4];
    float* out = (float*)d_out;

    float* aux_out = (out_size > T_TOK * DHID) ? out + (size_t)T_TOK * DHID : nullptr;

    cudaFuncSetAttribute(gemm_kernel, cudaFuncAttributeMaxDynamicSharedMemorySize, SMEM_DYN);

    initfill_kernel<<<(ROWS_CAP + 255) / 256, 256>>>(Wg);                    // 0
    conv_kernel<<<(int)((NW_CHUNKS + NX_CHUNKS) / 256), 256>>>(W, x);        // 1
    router_kernel<<<T_TOK / 32, 256>>>(x, bg);                               // 2
    finalize_kernel<<<1, 256>>>(aux_out);                                    // 3
    build_kernel<<<(T_TOK + 255) / 256, 256>>>();                            // 4
    gemm_kernel<<<dim3(DHID / BN, MTILES), 256, SMEM_DYN>>>();               // 5  <- ncu captures this
    combine_kernel<<<(T_TOK * DHID / 4 + 255) / 256, 256>>>(b, out);         // 6
}

// round 10
// speedup vs baseline: 1.0043x; 1.0021x over previous
#include <cuda_runtime.h>
#include <cuda_fp16.h>
#include <cstdint>
#include <cstddef>

// Problem constants
#define T_TOK 8192
#define DHID  1024
#define NE    8
#define TK    4

// GEMM config (fp16 single pass)
#define BM    128
#define BN    128
#define BKB   64                  // k per stage
#define NST   3
#define NK    (DHID / BKB)        // 16
#define MTILES 264
#define ROWS_CAP (MTILES * BM)    // 33792

// smem stage: A 128x64 fp16 (16KB, 128B rows, XOR swizzle) + B 64x128 fp16 (16KB, 256B rows)
#define A_OFF 0
#define B_OFF 16384
#define STAGE_BYTES 32768
#define SMEM_DYN (NST * STAGE_BYTES)   // 98304

// ---------------- scratch (device globals; no allocation) ----------------
__device__ __half g_Ah[(size_t)T_TOK * DHID];            // fp16(x)
__device__ __half g_Bh[(size_t)NE * DHID * DHID];        // fp16(W), [e][k][n]
__device__ __half g_Yh[(size_t)ROWS_CAP * DHID];         // fp16 GEMM results
__device__ float g_WgT[NE * DHID];                       // Wg transposed [e][d]
__device__ int   g_pair_tok[ROWS_CAP];
__device__ int   g_slot[T_TOK * TK];
__device__ int   g_topk_e[T_TOK * TK];
__device__ float g_topk_w[T_TOK * TK];
__device__ float g_probs[T_TOK * NE];
__device__ int   g_counts[NE];
__device__ int   g_cursor[NE];
__device__ int   g_off[NE + 1];

// ---------------- PTX helpers (sm_80-compatible) ----------------
__device__ __forceinline__ uint32_t h2_as_u32(__half2 h) {
    uint32_t u;
    *(__half2*)&u = h;
    return u;
}
__device__ __forceinline__ uint32_t smem_u32(const void* p) {
    uint32_t a;
    asm("{ .reg .u64 t; cvta.to.shared.u64 t, %1; cvt.u32.u64 %0, t; }" : "=r"(a) : "l"(p));
    return a;
}
__device__ __forceinline__ void cp16(uint32_t dst, const void* src) {
    asm volatile("cp.async.cg.shared.global [%0], [%1], 16;" :: "r"(dst), "l"(src));
}
__device__ __forceinline__ void cp16z(uint32_t dst, const void* src, int sz) {
    asm volatile("cp.async.cg.shared.global [%0], [%1], 16, %2;" :: "r"(dst), "l"(src), "r"(sz));
}
#define CP_COMMIT() asm volatile("cp.async.commit_group;" ::: "memory")
#define CP_WAIT(n)  asm volatile("cp.async.wait_group %0;" :: "n"(n) : "memory")

__device__ __forceinline__ void ldsm4(uint32_t* r, uint32_t addr) {
    asm volatile("ldmatrix.sync.aligned.m8n8.x4.shared.b16 {%0,%1,%2,%3}, [%4];"
        : "=r"(r[0]), "=r"(r[1]), "=r"(r[2]), "=r"(r[3]) : "r"(addr));
}
__device__ __forceinline__ void ldsm4t(uint32_t* r, uint32_t addr) {
    asm volatile("ldmatrix.sync.aligned.m8n8.x4.trans.shared.b16 {%0,%1,%2,%3}, [%4];"
        : "=r"(r[0]), "=r"(r[1]), "=r"(r[2]), "=r"(r[3]) : "r"(addr));
}
__device__ __forceinline__ void mma16816(float* c, const uint32_t* a, const uint32_t* b) {
    asm volatile("mma.sync.aligned.m16n8k16.row.col.f32.f16.f16.f32 "
        "{%0,%1,%2,%3}, {%4,%5,%6,%7}, {%8,%9}, {%0,%1,%2,%3};"
        : "+f"(c[0]), "+f"(c[1]), "+f"(c[2]), "+f"(c[3])
        : "r"(a[0]), "r"(a[1]), "r"(a[2]), "r"(a[3]), "r"(b[0]), "r"(b[1]));
}

// ---------------- kernel 0: counters + pad fill + WgT transpose ----------------
__global__ __launch_bounds__(256) void initfill_kernel(const float* __restrict__ Wg)
{
    int i = blockIdx.x * 256 + threadIdx.x;
    if (i < NE) { g_counts[i] = 0; g_cursor[i] = 0; }
    if (i < ROWS_CAP) g_pair_tok[i] = -1;
    if (i < NE * DHID) {
        // Wg[d][e] (i = d*8+e) -> WgT[e][d]
        g_WgT[(i & 7) * DHID + (i >> 3)] = Wg[i];
    }
}

// ---------------- kernel 1: W -> fp16 and x -> fp16 (merged) ----------------
#define NW_CHUNKS ((size_t)NE * DHID * DHID / 8)   // 1048576
#define NX_CHUNKS ((size_t)T_TOK * DHID / 8)       // 1048576
__global__ __launch_bounds__(256) void conv_kernel(
    const float* __restrict__ W, const float* __restrict__ x)
{
    size_t i = (size_t)blockIdx.x * 256 + threadIdx.x;
    const float* src;
    __half* dst;
    if (i < NW_CHUNKS) { src = W + i * 8; dst = g_Bh + i * 8; }
    else { size_t j = i - NW_CHUNKS; src = x + j * 8; dst = g_Ah + j * 8; }
    float4 a = ((const float4*)src)[0], c = ((const float4*)src)[1];
    __half2 h0 = __float22half2_rn(make_float2(a.x, a.y));
    __half2 h1 = __float22half2_rn(make_float2(a.z, a.w));
    __half2 h2 = __float22half2_rn(make_float2(c.x, c.y));
    __half2 h3 = __float22half2_rn(make_float2(c.z, c.w));
    *(uint4*)dst = make_uint4(h2_as_u32(h0), h2_as_u32(h1), h2_as_u32(h2), h2_as_u32(h3));
}

// ---------------- kernel 2: router (smem WgT, warp-per-token) ----------------
__global__ __launch_bounds__(256) void router_kernel(
    const float* __restrict__ x, const float* __restrict__ bg)
{
    __shared__ float wgs[NE * DHID];   // 32KB: wgs[e*1024 + d]
    for (int i = threadIdx.x; i < NE * DHID; i += 256)
        wgs[i] = g_WgT[i];
    __syncthreads();

    int warp = threadIdx.x >> 5, lane = threadIdx.x & 31;

    for (int tt = 0; tt < 4; tt++) {
        int t = blockIdx.x * 32 + tt * 8 + warp;
        const float* xr = x + (size_t)t * DHID;

        float xv[32];
#pragma unroll
        for (int i = 0; i < 32; i++) xv[i] = xr[lane + 32 * i];

        float acc[NE];
#pragma unroll
        for (int e = 0; e < NE; e++) acc[e] = 0.f;
#pragma unroll
        for (int e = 0; e < NE; e++) {
            const float* wr = wgs + e * DHID + lane;
#pragma unroll
            for (int i = 0; i < 32; i++)
                acc[e] = fmaf(xv[i], wr[32 * i], acc[e]);
        }
#pragma unroll
        for (int off = 16; off > 0; off >>= 1)
#pragma unroll
            for (int e = 0; e < NE; e++)
                acc[e] += __shfl_down_sync(0xffffffffu, acc[e], off);

        if (lane == 0) {
            float logit[NE], p[NE];
            float mx = -1e30f;
#pragma unroll
            for (int e = 0; e < NE; e++) {
                logit[e] = acc[e] + bg[e];
                mx = fmaxf(mx, logit[e]);
            }
            float sum = 0.f;
#pragma unroll
            for (int e = 0; e < NE; e++) { p[e] = __expf(logit[e] - mx); sum += p[e]; }
            float inv = 1.0f / sum;
#pragma unroll
            for (int e = 0; e < NE; e++) { p[e] *= inv; g_probs[t * NE + e] = p[e]; }

            bool used[NE];
#pragma unroll
            for (int e = 0; e < NE; e++) used[e] = false;
            int   idxs[TK];
            float vals[TK];
            float psel = 0.f;
#pragma unroll
            for (int k = 0; k < TK; k++) {
                int best = -1; float bv = -1.f;
#pragma unroll
                for (int e = 0; e < NE; e++)
                    if (!used[e] && p[e] > bv) { bv = p[e]; best = e; }
                used[best] = true;
                idxs[k] = best; vals[k] = bv; psel += bv;
            }
            float winv = 1.0f / (psel + 1e-6f);
#pragma unroll
            for (int k = 0; k < TK; k++) {
                g_topk_e[t * TK + k] = idxs[k];
                g_topk_w[t * TK + k] = vals[k] * winv;
                atomicAdd(&g_counts[idxs[k]], 1);
            }
        }
    }
}

// ---------------- kernel 3: deterministic probs reduce + scan + aux ----------------
__global__ __launch_bounds__(256) void finalize_kernel(float* aux_out)
{
    __shared__ float sh[256];
    int tid = threadIdx.x;
    int e = tid & 7, g = tid >> 3;
    float sum = 0.f;
    for (int t = g; t < T_TOK; t += 32) sum += g_probs[t * NE + e];
    sh[tid] = sum;
    __syncthreads();
#pragma unroll
    for (int st = 128; st >= 8; st >>= 1) {
        if (tid < st) sh[tid] += sh[tid + st];
        __syncthreads();
    }
    if (tid == 0) {
        int o = 0;
        g_off[0] = 0;
#pragma unroll
        for (int i = 0; i < NE; i++) {
            o += ((g_counts[i] + BM - 1) / BM) * BM;
            g_off[i + 1] = o;
        }
        float aux = 0.f;
#pragma unroll
        for (int i = 0; i < NE; i++) aux += (float)g_counts[i] * sh[i];
        aux *= (float)NE / ((float)T_TOK * (float)T_TOK);
        if (aux_out) *aux_out = aux;
    }
}

// ---------------- kernel 4: build pair list ----------------
__global__ void build_kernel() {
    int t = blockIdx.x * blockDim.x + threadIdx.x;
    if (t >= T_TOK) return;
#pragma unroll
    for (int k = 0; k < TK; k++) {
        int e = g_topk_e[t * TK + k];
        int pos = g_off[e] + atomicAdd(&g_cursor[e], 1);
        g_pair_tok[pos] = t;
        g_slot[t * TK + k] = pos;
    }
}

// ---------------- kernel 5: grouped fp16 mma.sync GEMM ----------------
__global__ __launch_bounds__(256, 2) void gemm_kernel()
{
    extern __shared__ char dsm[];
    const int off8 = g_off[NE];
    const int m0 = blockIdx.y * BM;
    if (m0 >= off8) return;
    const int n0 = blockIdx.x * BN;
    const int tid = threadIdx.x;
    const int lane = tid & 31, wid = tid >> 5;

    int e = 0;
#pragma unroll
    for (int i = 1; i < NE; i++) if (m0 >= g_off[i]) e = i;
    const __half* __restrict__ Be = g_Bh + (size_t)e * DHID * DHID;

    const uint32_t sb = smem_u32(dsm);

    // A loader: thread t -> row t>>1, chunks (t&1)*4..+3 (16B chunks of 128B row)
    const int arow = tid >> 1;
    const int ac0  = (tid & 1) * 4;
    const int tok = g_pair_tok[m0 + arow];
    const __half* asrc0 = g_Ah + (size_t)(tok < 0 ? 0 : tok) * DHID;
    const int asz = (tok < 0) ? 0 : 16;
    // B loader: thread t -> krow t>>2, chunks (t&3)*4..+3 (16B chunks of 256B row)
    const int brow = tid >> 2;
    const int bc0  = (tid & 3) * 4;

    auto load_stage = [&](int st, int kt) {
        uint32_t stg = sb + st * STAGE_BYTES;
        int kb = kt * BKB;
        const char* as = (const char*)(asrc0 + kb + ac0 * 8);
        uint32_t ad = stg + A_OFF + arow * 128;
        int ar7 = arow & 7;
#pragma unroll
        for (int c = 0; c < 4; c++)
            cp16z(ad + (((ac0 + c) ^ ar7) << 4), as + c * 16, asz);
        const char* bs = (const char*)(Be + (size_t)(kb + brow) * DHID + n0 + bc0 * 8);
        uint32_t bd = stg + B_OFF + brow * 256;
        int br7 = brow & 7;
#pragma unroll
        for (int c = 0; c < 4; c++)
            cp16(bd + (((bc0 + c) ^ br7) << 4), bs + c * 16);
    };

    const int wm = (wid & 1) * 64;           // warp m-offset
    const int wn = (wid >> 1) * 32;          // warp n-offset

    float acc[4][4][4];
#pragma unroll
    for (int a = 0; a < 4; a++)
#pragma unroll
        for (int b = 0; b < 4; b++)
#pragma unroll
            for (int c = 0; c < 4; c++) acc[a][b][c] = 0.f;

    load_stage(0, 0); CP_COMMIT();
    load_stage(1, 1); CP_COMMIT();

    const int l15 = lane & 15;
    const int l4  = lane >> 4;

    for (int kt = 0; kt < NK; kt++) {
        if (kt + 2 < NK) load_stage((kt + 2) % NST, kt + 2);
        CP_COMMIT();
        CP_WAIT(2);
        __syncthreads();

        uint32_t stg = sb + (kt % NST) * STAGE_BYTES;
        uint32_t aB = stg + A_OFF;
        uint32_t bB = stg + B_OFF;
#pragma unroll
        for (int kk = 0; kk < 4; kk++) {
            uint32_t a[4][4], bf[2][4];
#pragma unroll
            for (int mi = 0; mi < 4; mi++) {
                int row = wm + mi * 16 + l15;
                int c = kk * 2 + l4;
                ldsm4(a[mi], aB + row * 128 + ((c ^ (row & 7)) << 4));
            }
#pragma unroll
            for (int nh = 0; nh < 2; nh++) {
                int row = kk * 16 + l15;
                int c = (wn >> 3) + nh * 2 + l4;
                ldsm4t(bf[nh], bB + row * 256 + ((c ^ (row & 7)) << 4));
            }
#pragma unroll
            for (int mi = 0; mi < 4; mi++)
#pragma unroll
                for (int nj = 0; nj < 4; nj++)
                    mma16816(acc[mi][nj], a[mi], &bf[nj >> 1][(nj & 1) * 2]);
        }
        __syncthreads();
    }

    // epilogue: registers -> g_Yh (fp16)
#pragma unroll
    for (int mi = 0; mi < 4; mi++) {
        int r0 = m0 + wm + mi * 16 + (lane >> 2);
#pragma unroll
        for (int nj = 0; nj < 4; nj++) {
            int c0 = n0 + wn + nj * 8 + (lane & 3) * 2;
            __half2 lo = __float22half2_rn(make_float2(acc[mi][nj][0], acc[mi][nj][1]));
            __half2 hi = __float22half2_rn(make_float2(acc[mi][nj][2], acc[mi][nj][3]));
            *(__half2*)(g_Yh + (size_t)r0 * DHID + c0)       = lo;
            *(__half2*)(g_Yh + (size_t)(r0 + 8) * DHID + c0) = hi;
        }
    }
}

// ---------------- kernel 6: weighted combine (fp16 Y) ----------------
__global__ __launch_bounds__(256) void combine_kernel(
    const float* __restrict__ b, float* __restrict__ out)
{
    int idx = blockIdx.x * blockDim.x + threadIdx.x;
    int t = idx >> 8;
    int f = (idx & 255) << 2;
    float4 r = make_float4(0.f, 0.f, 0.f, 0.f);
#pragma unroll
    for (int k = 0; k < TK; k++) {
        int e   = g_topk_e[t * TK + k];
        float w = g_topk_w[t * TK + k];
        int sl  = g_slot[t * TK + k];
        uint2 yraw = *(const uint2*)(g_Yh + (size_t)sl * DHID + f);
        float2 y01 = __half22float2(*(__half2*)&yraw.x);
        float2 y23 = __half22float2(*(__half2*)&yraw.y);
        float4 bv = *(const float4*)(b + (size_t)e * DHID + f);
        r.x = fmaf(w, y01.x + bv.x, r.x);
        r.y = fmaf(w, y01.y + bv.y, r.y);
        r.z = fmaf(w, y23.x + bv.z, r.z);
        r.w = fmaf(w, y23.y + bv.w, r.w);
    }
    *(float4*)(out + (size_t)t * DHID + f) = r;
}

// ---------------- launch ----------------
extern "C" void kernel_launch(void* const* d_in, const int* in_sizes, int n_in,
                              void* d_out, int out_size)
{
    const float* x  = (const float*)d_in[0];
    const float* Wg = (const float*)d_in[1];
    const float* bg = (const float*)d_in[2];
    const float* W  = (const float*)d_in[3];
    const float* b  = (const float*)d_in[4];
    float* out = (float*)d_out;

    float* aux_out = (out_size > T_TOK * DHID) ? out + (size_t)T_TOK * DHID : nullptr;

    cudaFuncSetAttribute(gemm_kernel, cudaFuncAttributeMaxDynamicSharedMemorySize, SMEM_DYN);

    initfill_kernel<<<(ROWS_CAP + 255) / 256, 256>>>(Wg);                    // 0
    conv_kernel<<<(int)((NW_CHUNKS + NX_CHUNKS) / 256), 256>>>(W, x);        // 1
    router_kernel<<<T_TOK / 32, 256>>>(x, bg);                               // 2
    finalize_kernel<<<1, 256>>>(aux_out);                                    // 3
    build_kernel<<<(T_TOK + 255) / 256, 256>>>();                            // 4
    gemm_kernel<<<dim3(DHID / BN, MTILES), 256, SMEM_DYN>>>();               // 5  <- ncu captures this
    combine_kernel<<<(T_TOK * DHID / 4 + 255) / 256, 256>>>(b, out);         // 6
}